// round 2
// baseline (speedup 1.0000x reference)
#include <cuda_runtime.h>
#include <math.h>
#include <stdint.h>

#define PP 7
#define NTOK 8192
#define DD 1024
#define HH 16
#define HDIM 64

// ---------------- scratch (device globals; no allocation allowed) --------
__device__ __align__(16) float g_wqt[HH * DD];                 // [h][d]  = Wk[:,hb] @ q_h
__device__ float g_s0[HH];                                     // bk[hb] . q_h
__device__ __align__(16) float g_cvec[DD];                     // bv @ Wo + bo
__device__ __align__(16) float g_scores[(size_t)PP * NTOK * HH];   // [p][n][h]
__device__ __align__(16) float g_attn[(size_t)NTOK * HH * 8];      // [n][h][p], p padded to 8
__device__ __align__(16) float g_xw[(size_t)HH * NTOK * DD];       // [h][n][d]  (537 MB)
__device__ __align__(16) float g_G[(size_t)NTOK * DD];             // attn_out [n][m]

// ---------------- K0a: wq[h][d] = sum_j Wk[d][64h+j] * q[h][j] -----------
__global__ void k0_wq(const float* __restrict__ pq, const float* __restrict__ Wk,
                      const int* __restrict__ bidx) {
    int w = (blockIdx.x * blockDim.x + threadIdx.x) >> 5;   // 16384 warps
    int lane = threadIdx.x & 31;
    int h = w >> 10;
    int d = w & 1023;
    const float* q = pq + (size_t)bidx[0] * HH * HDIM + h * HDIM;
    const float* wrow = Wk + (size_t)d * DD + h * HDIM;
    float s = wrow[lane] * q[lane] + wrow[lane + 32] * q[lane + 32];
#pragma unroll
    for (int o = 16; o; o >>= 1) s += __shfl_xor_sync(0xFFFFFFFFu, s, o);
    if (lane == 0) g_wqt[h * DD + d] = s;
}

// ---------------- K0b: cvec = bv @ Wo + bo ;  s0[h] = bk[hb].q_h ----------
__global__ void k0_misc(const float* __restrict__ pq, const float* __restrict__ bk,
                        const float* __restrict__ bv, const float* __restrict__ Wo,
                        const float* __restrict__ bo, const int* __restrict__ bidx) {
    int t = blockIdx.x * 256 + threadIdx.x;
    if (t < DD) {
        float acc = bo[t];
#pragma unroll 8
        for (int d = 0; d < DD; d++) acc = fmaf(bv[d], Wo[(size_t)d * DD + t], acc);
        g_cvec[t] = acc;
    }
    if (blockIdx.x == 4 && threadIdx.x < HH) {
        int h = threadIdx.x;
        const float* q = pq + (size_t)bidx[0] * HH * HDIM + h * HDIM;
        float s = 0.f;
#pragma unroll
        for (int j = 0; j < HDIM; j++) s = fmaf(bk[h * HDIM + j], q[j], s);
        g_s0[h] = s;
    }
}

// ---------------- K1: scores[p][n][h] = 0.125*(x[p,n,:].wq_h + s0[h]) -----
__global__ __launch_bounds__(256) void k1_scores(const float* __restrict__ x) {
    int w = (blockIdx.x * blockDim.x + threadIdx.x) >> 5;   // 57344 warps = one per (p,n)
    int lane = threadIdx.x & 31;
    int p = w / NTOK;
    int n = w - p * NTOK;
    const float4* xv = (const float4*)(x + ((size_t)p * NTOK + n) * DD);
    const float4* wqv = (const float4*)g_wqt;               // [h][256] float4s
    float acc[HH];
#pragma unroll
    for (int h = 0; h < HH; h++) acc[h] = 0.f;
#pragma unroll
    for (int i = 0; i < 8; i++) {
        float4 xx = xv[i * 32 + lane];
#pragma unroll
        for (int h = 0; h < HH; h++) {
            float4 ww = wqv[h * 256 + i * 32 + lane];
            acc[h] = fmaf(xx.x, ww.x, acc[h]);
            acc[h] = fmaf(xx.y, ww.y, acc[h]);
            acc[h] = fmaf(xx.z, ww.z, acc[h]);
            acc[h] = fmaf(xx.w, ww.w, acc[h]);
        }
    }
#pragma unroll
    for (int h = 0; h < HH; h++)
#pragma unroll
        for (int o = 16; o; o >>= 1) acc[h] += __shfl_xor_sync(0xFFFFFFFFu, acc[h], o);
    if (lane < HH) {
        float v = 0.f;
#pragma unroll
        for (int h = 0; h < HH; h++)
            if (lane == h) v = acc[h];
        g_scores[((size_t)p * NTOK + n) * HH + lane] = 0.125f * (v + g_s0[lane]);
    }
}

// ---------------- K2: softmax over p -------------------------------------
__global__ void k2_softmax() {
    int t = blockIdx.x * blockDim.x + threadIdx.x;   // n*H + h, 131072 total
    int n = t >> 4;
    int h = t & 15;
    float s[PP];
    float mx = -1e30f;
#pragma unroll
    for (int p = 0; p < PP; p++) {
        s[p] = g_scores[((size_t)p * NTOK + n) * HH + h];
        mx = fmaxf(mx, s[p]);
    }
    float sum = 0.f;
#pragma unroll
    for (int p = 0; p < PP; p++) {
        s[p] = expf(s[p] - mx);
        sum += s[p];
    }
    float inv = 1.f / sum;
#pragma unroll
    for (int p = 0; p < PP; p++) g_attn[(size_t)n * HH * 8 + h * 8 + p] = s[p] * inv;
}

// ---------------- K3a: XW[h][n][d] = sum_p attn[n,h,p]*x[p,n,d] ----------
__global__ __launch_bounds__(256) void k3a_xw(const float* __restrict__ x) {
    int n = blockIdx.x;
    int t = threadIdx.x;   // 256 threads -> one float4 of d each
    __shared__ float sa[HH * 8];
    if (t < HH * 8) sa[t] = g_attn[(size_t)n * HH * 8 + t];
    __syncthreads();
    const float4* xv = (const float4*)x;
    float4 xr[PP];
#pragma unroll
    for (int p = 0; p < PP; p++) xr[p] = xv[((size_t)p * NTOK + n) * 256 + t];
    float4* ow = (float4*)g_xw;
#pragma unroll
    for (int h = 0; h < HH; h++) {
        float4 o = make_float4(0.f, 0.f, 0.f, 0.f);
#pragma unroll
        for (int p = 0; p < PP; p++) {
            float a = sa[h * 8 + p];
            o.x = fmaf(a, xr[p].x, o.x);
            o.y = fmaf(a, xr[p].y, o.y);
            o.z = fmaf(a, xr[p].z, o.z);
            o.w = fmaf(a, xr[p].w, o.w);
        }
        ow[((size_t)h * NTOK + n) * 256 + t] = o;
    }
}

// ---------------- tf32 tensor-core GEMM, 128x64 tile ----------------------
// mode 0: C=g_G (col block by=head), A=g_xw[head], B=Wv, bias=none
// mode 1: C=out, A=g_G,                           B=Wo, bias=g_cvec
#define BM 128
#define BN 64
#define BK 32

__device__ __forceinline__ float to_tf32(float x) {
    uint32_t u;
    asm("cvt.rna.tf32.f32 %0, %1;" : "=r"(u) : "f"(x));
    return __uint_as_float(u);
}

__device__ __forceinline__ void mma_tf32(float* d, const uint32_t* a, const uint32_t* b) {
    asm volatile(
        "mma.sync.aligned.m16n8k8.row.col.f32.tf32.tf32.f32 "
        "{%0,%1,%2,%3}, {%4,%5,%6,%7}, {%8,%9}, {%0,%1,%2,%3};"
        : "+f"(d[0]), "+f"(d[1]), "+f"(d[2]), "+f"(d[3])
        : "r"(a[0]), "r"(a[1]), "r"(a[2]), "r"(a[3]), "r"(b[0]), "r"(b[1]));
}

__global__ __launch_bounds__(256) void gemm_tf32(int mode, const float* __restrict__ Bmat,
                                                 float* __restrict__ Cout) {
    __shared__ float As[BM][BK + 4];   // 128 x 36 : frag addr ≡ 4g+tig (conflict-free)
    __shared__ float Bs[BK][BN + 8];   // 32 x 72  : frag addr ≡ 8tig+g (conflict-free)
    int by = blockIdx.y;
    const float* A;
    float* C;
    const float* bias;
    if (mode == 0) {
        A = g_xw + (size_t)by * NTOK * DD;
        C = g_G;
        bias = nullptr;
    } else {
        A = g_G;
        C = Cout;
        bias = g_cvec;
    }
    const float* Ab = A + (size_t)blockIdx.x * BM * DD;
    const float* Bb = Bmat + by * BN;

    int tid = threadIdx.x;
    int warp = tid >> 5, lane = tid & 31;
    int wm = warp & 3, wn = warp >> 2;   // 4 x 2 warp grid; warp tile 32x32
    int g = lane >> 2, tig = lane & 3;
    int rb = wm * 32;
    int nb0 = wn * 32;

    float acc[2][4][4];
#pragma unroll
    for (int i = 0; i < 2; i++)
#pragma unroll
        for (int j = 0; j < 4; j++)
#pragma unroll
            for (int v = 0; v < 4; v++) acc[i][j][v] = 0.f;

    for (int k0 = 0; k0 < DD; k0 += BK) {
        // A tile 128x32 (float4 along k, cvt, STS128)
#pragma unroll
        for (int i = 0; i < 4; i++) {
            int idx = tid + 256 * i;
            int r = idx >> 3, c4 = (idx & 7) * 4;
            float4 v = *(const float4*)(Ab + (size_t)r * DD + k0 + c4);
            v.x = to_tf32(v.x); v.y = to_tf32(v.y); v.z = to_tf32(v.z); v.w = to_tf32(v.w);
            *(float4*)&As[r][c4] = v;
        }
        // B tile 32x64 (float4 along n)
#pragma unroll
        for (int i = 0; i < 2; i++) {
            int idx = tid + 256 * i;
            int kk = idx >> 4, c4 = (idx & 15) * 4;
            float4 v = *(const float4*)(Bb + (size_t)(k0 + kk) * DD + c4);
            v.x = to_tf32(v.x); v.y = to_tf32(v.y); v.z = to_tf32(v.z); v.w = to_tf32(v.w);
            *(float4*)&Bs[kk][c4] = v;
        }
        __syncthreads();
#pragma unroll
        for (int ks = 0; ks < 4; ks++) {
            int kk = ks * 8;
            uint32_t a[2][4], b[4][2];
#pragma unroll
            for (int mt = 0; mt < 2; mt++) {
                int r0 = rb + mt * 16;
                a[mt][0] = __float_as_uint(As[r0 + g][kk + tig]);
                a[mt][1] = __float_as_uint(As[r0 + g + 8][kk + tig]);
                a[mt][2] = __float_as_uint(As[r0 + g][kk + tig + 4]);
                a[mt][3] = __float_as_uint(As[r0 + g + 8][kk + tig + 4]);
            }
#pragma unroll
            for (int nt = 0; nt < 4; nt++) {
                int n0 = nb0 + nt * 8;
                b[nt][0] = __float_as_uint(Bs[kk + tig][n0 + g]);
                b[nt][1] = __float_as_uint(Bs[kk + tig + 4][n0 + g]);
            }
#pragma unroll
            for (int mt = 0; mt < 2; mt++)
#pragma unroll
                for (int nt = 0; nt < 4; nt++) mma_tf32(acc[mt][nt], a[mt], b[nt]);
        }
        __syncthreads();
    }

    // epilogue: c0,c1 -> (row, 2tig..2tig+1); c2,c3 -> (row+8, ...)
#pragma unroll
    for (int mt = 0; mt < 2; mt++) {
#pragma unroll
        for (int nt = 0; nt < 4; nt++) {
            size_t row0 = (size_t)blockIdx.x * BM + rb + mt * 16 + g;
            int col = by * BN + nb0 + nt * 8 + tig * 2;
            float2 lo = make_float2(acc[mt][nt][0], acc[mt][nt][1]);
            float2 hi = make_float2(acc[mt][nt][2], acc[mt][nt][3]);
            if (bias) {
                float2 bb = *(const float2*)(bias + col);
                lo.x += bb.x; lo.y += bb.y;
                hi.x += bb.x; hi.y += bb.y;
            }
            *(float2*)(C + row0 * DD + col) = lo;
            *(float2*)(C + (row0 + 8) * DD + col) = hi;
        }
    }
}

// ---------------- launch ---------------------------------------------------
extern "C" void kernel_launch(void* const* d_in, const int* in_sizes, int n_in,
                              void* d_out, int out_size) {
    const float* prev = (const float*)d_in[0];   // [7,4,2048,1024]
    const float* pq   = (const float*)d_in[1];   // [8,16,64]
    const float* Wk   = (const float*)d_in[2];
    const float* bk   = (const float*)d_in[3];
    const float* Wv   = (const float*)d_in[4];
    const float* bv   = (const float*)d_in[5];
    const float* Wo   = (const float*)d_in[6];
    const float* bo   = (const float*)d_in[7];
    const int*   bidx = (const int*)d_in[8];
    float* out = (float*)d_out;

    k0_wq<<<2048, 256>>>(pq, Wk, bidx);
    k0_misc<<<5, 256>>>(pq, bk, bv, Wo, bo, bidx);
    k1_scores<<<7168, 256>>>(prev);
    k2_softmax<<<512, 256>>>();
    k3a_xw<<<NTOK, 256>>>(prev);
    gemm_tf32<<<dim3(NTOK / BM, 16), 256>>>(0, Wv, out);   // G = per-head XW @ Wv
    gemm_tf32<<<dim3(NTOK / BM, 16), 256>>>(1, Wo, out);   // out = G @ Wo + cvec
}

// round 3
// speedup vs baseline: 1.4790x; 1.4790x over previous
#include <cuda_runtime.h>
#include <cuda_fp16.h>
#include <math.h>
#include <stdint.h>

#define PP 7
#define NTOK 8192
#define DD 1024
#define HH 16
#define HDIM 64

// ---------------- scratch (device globals; no allocation allowed) --------
__device__ __align__(16) float g_wqt[HH * DD];                 // [h][d]  = Wk[:,hb] @ q_h
__device__ float g_s0[HH];                                     // bk[hb] . q_h
__device__ __align__(16) float g_cvec[DD];                     // bv @ Wo + bo
__device__ __align__(16) float g_scores[(size_t)PP * NTOK * HH];   // [p][n][h]
__device__ __align__(16) float g_attn[(size_t)NTOK * HH * 8];      // [n][h][p], p padded to 8
__device__ __align__(16) __half g_xw_h[(size_t)HH * NTOK * DD];    // [h][n][d] fp16 (268 MB)
__device__ __align__(16) __half g_G_h[(size_t)NTOK * DD];          // attn_out fp16
__device__ __align__(16) __half g_wv_h[(size_t)DD * DD];           // Wv transposed [n][k] fp16
__device__ __align__(16) __half g_wo_h[(size_t)DD * DD];           // Wo transposed [n][k] fp16

// ---------------- K0a: wq[h][d] = sum_j Wk[d][64h+j] * q[h][j] -----------
__global__ void k0_wq(const float* __restrict__ pq, const float* __restrict__ Wk,
                      const int* __restrict__ bidx) {
    int w = (blockIdx.x * blockDim.x + threadIdx.x) >> 5;
    int lane = threadIdx.x & 31;
    int h = w >> 10;
    int d = w & 1023;
    const float* q = pq + (size_t)bidx[0] * HH * HDIM + h * HDIM;
    const float* wrow = Wk + (size_t)d * DD + h * HDIM;
    float s = wrow[lane] * q[lane] + wrow[lane + 32] * q[lane + 32];
#pragma unroll
    for (int o = 16; o; o >>= 1) s += __shfl_xor_sync(0xFFFFFFFFu, s, o);
    if (lane == 0) g_wqt[h * DD + d] = s;
}

// ---------------- K0b: cvec = bv @ Wo + bo ;  s0[h] = bk[hb].q_h ----------
__global__ void k0_misc(const float* __restrict__ pq, const float* __restrict__ bk,
                        const float* __restrict__ bv, const float* __restrict__ Wo,
                        const float* __restrict__ bo, const int* __restrict__ bidx) {
    int t = blockIdx.x * 256 + threadIdx.x;
    if (t < DD) {
        float acc = bo[t];
#pragma unroll 8
        for (int d = 0; d < DD; d++) acc = fmaf(bv[d], Wo[(size_t)d * DD + t], acc);
        g_cvec[t] = acc;
    }
    if (blockIdx.x == 4 && threadIdx.x < HH) {
        int h = threadIdx.x;
        const float* q = pq + (size_t)bidx[0] * HH * HDIM + h * HDIM;
        float s = 0.f;
#pragma unroll
        for (int j = 0; j < HDIM; j++) s = fmaf(bk[h * HDIM + j], q[j], s);
        g_s0[h] = s;
    }
}

// ---------------- K0c: transpose+convert Wv, Wo -> [n][k] fp16 ----------
__global__ void k0_conv(const float* __restrict__ Wv, const float* __restrict__ Wo) {
    __shared__ float tile[32][33];
    const float* W = blockIdx.z ? Wo : Wv;
    __half* O = blockIdx.z ? g_wo_h : g_wv_h;
    int bx = blockIdx.x * 32, by = blockIdx.y * 32;
#pragma unroll
    for (int yy = threadIdx.y; yy < 32; yy += 8)
        tile[yy][threadIdx.x] = W[(size_t)(by + yy) * DD + bx + threadIdx.x];
    __syncthreads();
#pragma unroll
    for (int yy = threadIdx.y; yy < 32; yy += 8)
        O[(size_t)(bx + yy) * DD + by + threadIdx.x] = __float2half(tile[threadIdx.x][yy]);
}

// ---------------- K1: scores[p][n][h] = 0.125*(x[p,n,:].wq_h + s0[h]) -----
__global__ __launch_bounds__(256) void k1_scores(const float* __restrict__ x) {
    int w = (blockIdx.x * blockDim.x + threadIdx.x) >> 5;
    int lane = threadIdx.x & 31;
    int p = w / NTOK;
    int n = w - p * NTOK;
    const float4* xv = (const float4*)(x + ((size_t)p * NTOK + n) * DD);
    const float4* wqv = (const float4*)g_wqt;
    float acc[HH];
#pragma unroll
    for (int h = 0; h < HH; h++) acc[h] = 0.f;
#pragma unroll
    for (int i = 0; i < 8; i++) {
        float4 xx = xv[i * 32 + lane];
#pragma unroll
        for (int h = 0; h < HH; h++) {
            float4 ww = wqv[h * 256 + i * 32 + lane];
            acc[h] = fmaf(xx.x, ww.x, acc[h]);
            acc[h] = fmaf(xx.y, ww.y, acc[h]);
            acc[h] = fmaf(xx.z, ww.z, acc[h]);
            acc[h] = fmaf(xx.w, ww.w, acc[h]);
        }
    }
#pragma unroll
    for (int h = 0; h < HH; h++)
#pragma unroll
        for (int o = 16; o; o >>= 1) acc[h] += __shfl_xor_sync(0xFFFFFFFFu, acc[h], o);
    if (lane < HH) {
        float v = 0.f;
#pragma unroll
        for (int h = 0; h < HH; h++)
            if (lane == h) v = acc[h];
        g_scores[((size_t)p * NTOK + n) * HH + lane] = 0.125f * (v + g_s0[lane]);
    }
}

// ---------------- K2: softmax over p -------------------------------------
__global__ void k2_softmax() {
    int t = blockIdx.x * blockDim.x + threadIdx.x;
    int n = t >> 4;
    int h = t & 15;
    float s[PP];
    float mx = -1e30f;
#pragma unroll
    for (int p = 0; p < PP; p++) {
        s[p] = g_scores[((size_t)p * NTOK + n) * HH + h];
        mx = fmaxf(mx, s[p]);
    }
    float sum = 0.f;
#pragma unroll
    for (int p = 0; p < PP; p++) {
        s[p] = expf(s[p] - mx);
        sum += s[p];
    }
    float inv = 1.f / sum;
#pragma unroll
    for (int p = 0; p < PP; p++) g_attn[(size_t)n * HH * 8 + h * 8 + p] = s[p] * inv;
}

// ---------------- K3a: XW_h[h][n][d] = sum_p attn[n,h,p]*x[p,n,d] (fp16) --
__global__ __launch_bounds__(256) void k3a_xw(const float* __restrict__ x) {
    int n = blockIdx.x;
    int t = threadIdx.x;
    __shared__ float sa[HH * 8];
    if (t < HH * 8) sa[t] = g_attn[(size_t)n * HH * 8 + t];
    __syncthreads();
    const float4* xv = (const float4*)x;
    float4 xr[PP];
#pragma unroll
    for (int p = 0; p < PP; p++) xr[p] = xv[((size_t)p * NTOK + n) * 256 + t];
#pragma unroll
    for (int h = 0; h < HH; h++) {
        float4 o = make_float4(0.f, 0.f, 0.f, 0.f);
#pragma unroll
        for (int p = 0; p < PP; p++) {
            float a = sa[h * 8 + p];
            o.x = fmaf(a, xr[p].x, o.x);
            o.y = fmaf(a, xr[p].y, o.y);
            o.z = fmaf(a, xr[p].z, o.z);
            o.w = fmaf(a, xr[p].w, o.w);
        }
        __half2 h0 = __floats2half2_rn(o.x, o.y);
        __half2 h1 = __floats2half2_rn(o.z, o.w);
        uint2 pk;
        pk.x = *(uint32_t*)&h0;
        pk.y = *(uint32_t*)&h1;
        *(uint2*)(g_xw_h + ((size_t)h * NTOK + n) * DD + t * 4) = pk;
    }
}

// ---------------- fp16 tensor-core GEMM, 128x64x32, cp.async 2-stage ------
// mode 0: C=g_G_h (fp16), A=g_xw_h[head by], B=g_wv_h, bias none
// mode 1: C=out (fp32),   A=g_G_h,          B=g_wo_h, bias g_cvec
#define BM 128
#define BN 64
#define BK 32
#define LDS_A 40   // halves per padded row (80 B; gcd(80,128)=16 -> conflict-free)

__device__ __forceinline__ void cp16(void* dst, const void* src) {
    uint32_t d = (uint32_t)__cvta_generic_to_shared(dst);
    asm volatile("cp.async.cg.shared.global [%0], [%1], 16;" :: "r"(d), "l"(src));
}

__device__ __forceinline__ void mma_f16(float* d, const uint32_t* a, const uint32_t* b) {
    asm volatile(
        "mma.sync.aligned.m16n8k16.row.col.f32.f16.f16.f32 "
        "{%0,%1,%2,%3}, {%4,%5,%6,%7}, {%8,%9}, {%0,%1,%2,%3};"
        : "+f"(d[0]), "+f"(d[1]), "+f"(d[2]), "+f"(d[3])
        : "r"(a[0]), "r"(a[1]), "r"(a[2]), "r"(a[3]), "r"(b[0]), "r"(b[1]));
}

__global__ __launch_bounds__(256) void gemm_f16(int mode, float* __restrict__ Cout) {
    __shared__ __align__(16) __half As[2][BM][LDS_A];
    __shared__ __align__(16) __half Bs[2][BN][LDS_A];
    int by = blockIdx.y;
    const __half* A = (mode == 0) ? (g_xw_h + (size_t)by * NTOK * DD) : g_G_h;
    const __half* Bw = (mode == 0) ? g_wv_h : g_wo_h;
    const __half* Ab = A + (size_t)blockIdx.x * BM * DD;
    const __half* Bb = Bw + (size_t)by * BN * DD;

    int tid = threadIdx.x;
    int warp = tid >> 5, lane = tid & 31;
    int wm = warp & 3, wn = warp >> 2;       // 4x2 warp grid, warp tile 32x32
    int g = lane >> 2, tig = lane & 3;
    int rb = wm * 32, nb0 = wn * 32;

    float acc[2][4][4];
#pragma unroll
    for (int i = 0; i < 2; i++)
#pragma unroll
        for (int j = 0; j < 4; j++)
#pragma unroll
            for (int v = 0; v < 4; v++) acc[i][j][v] = 0.f;

    // stage loader: A tile 128x32 halves (512 x 16B), B tile 64x32 (256 x 16B)
    int ar = tid >> 2, ac = (tid & 3) * 8;           // A chunk row/col (first half)
    int ar2 = (tid + 256) >> 2;                      // second half rows 64..127
    int br = tid >> 2, bc = (tid & 3) * 8;

#define LOAD_STAGE(s, k0)                                                     \
    do {                                                                      \
        cp16(&As[s][ar][ac], Ab + (size_t)ar * DD + (k0) + ac);               \
        cp16(&As[s][ar2][ac], Ab + (size_t)ar2 * DD + (k0) + ac);             \
        cp16(&Bs[s][br][bc], Bb + (size_t)br * DD + (k0) + bc);               \
        asm volatile("cp.async.commit_group;");                               \
    } while (0)

    LOAD_STAGE(0, 0);
    const int NIT = DD / BK;   // 32
    for (int it = 0; it < NIT; it++) {
        if (it + 1 < NIT) {
            LOAD_STAGE((it + 1) & 1, (it + 1) * BK);
            asm volatile("cp.async.wait_group 1;");
        } else {
            asm volatile("cp.async.wait_group 0;");
        }
        __syncthreads();
        int s = it & 1;
#pragma unroll
        for (int kt = 0; kt < 2; kt++) {
            int kk = kt * 16;
            uint32_t a[2][4], b[4][2];
#pragma unroll
            for (int mt = 0; mt < 2; mt++) {
                int r0 = rb + mt * 16;
                a[mt][0] = *(const uint32_t*)&As[s][r0 + g][kk + 2 * tig];
                a[mt][1] = *(const uint32_t*)&As[s][r0 + g + 8][kk + 2 * tig];
                a[mt][2] = *(const uint32_t*)&As[s][r0 + g][kk + 8 + 2 * tig];
                a[mt][3] = *(const uint32_t*)&As[s][r0 + g + 8][kk + 8 + 2 * tig];
            }
#pragma unroll
            for (int nt = 0; nt < 4; nt++) {
                int n0 = nb0 + nt * 8;
                b[nt][0] = *(const uint32_t*)&Bs[s][n0 + g][kk + 2 * tig];
                b[nt][1] = *(const uint32_t*)&Bs[s][n0 + g][kk + 8 + 2 * tig];
            }
#pragma unroll
            for (int mt = 0; mt < 2; mt++)
#pragma unroll
                for (int nt = 0; nt < 4; nt++) mma_f16(acc[mt][nt], a[mt], b[nt]);
        }
        __syncthreads();
    }

    // epilogue
#pragma unroll
    for (int mt = 0; mt < 2; mt++) {
#pragma unroll
        for (int nt = 0; nt < 4; nt++) {
            size_t row0 = (size_t)blockIdx.x * BM + rb + mt * 16 + g;
            int col = by * BN + nb0 + nt * 8 + tig * 2;
            if (mode == 0) {
                __half2 lo = __floats2half2_rn(acc[mt][nt][0], acc[mt][nt][1]);
                __half2 hi = __floats2half2_rn(acc[mt][nt][2], acc[mt][nt][3]);
                *(__half2*)(g_G_h + row0 * DD + col) = lo;
                *(__half2*)(g_G_h + (row0 + 8) * DD + col) = hi;
            } else {
                float2 bb = *(const float2*)(g_cvec + col);
                float2 lo = make_float2(acc[mt][nt][0] + bb.x, acc[mt][nt][1] + bb.y);
                float2 hi = make_float2(acc[mt][nt][2] + bb.x, acc[mt][nt][3] + bb.y);
                *(float2*)(Cout + row0 * DD + col) = lo;
                *(float2*)(Cout + (row0 + 8) * DD + col) = hi;
            }
        }
    }
}

// ---------------- launch ---------------------------------------------------
extern "C" void kernel_launch(void* const* d_in, const int* in_sizes, int n_in,
                              void* d_out, int out_size) {
    const float* prev = (const float*)d_in[0];   // [7,4,2048,1024]
    const float* pq   = (const float*)d_in[1];   // [8,16,64]
    const float* Wk   = (const float*)d_in[2];
    const float* bk   = (const float*)d_in[3];
    const float* Wv   = (const float*)d_in[4];
    const float* bv   = (const float*)d_in[5];
    const float* Wo   = (const float*)d_in[6];
    const float* bo   = (const float*)d_in[7];
    const int*   bidx = (const int*)d_in[8];
    float* out = (float*)d_out;

    k0_wq<<<2048, 256>>>(pq, Wk, bidx);
    k0_misc<<<5, 256>>>(pq, bk, bv, Wo, bo, bidx);
    k0_conv<<<dim3(32, 32, 2), dim3(32, 8)>>>(Wv, Wo);
    k1_scores<<<7168, 256>>>(prev);
    k2_softmax<<<512, 256>>>();
    k3a_xw<<<NTOK, 256>>>(prev);
    gemm_f16<<<dim3(NTOK / BM, 16), 256>>>(0, out);   // G = per-head XW @ Wv
    gemm_f16<<<dim3(NTOK / BM, 16), 256>>>(1, out);   // out = G @ Wo + cvec
}

// round 5
// speedup vs baseline: 1.8030x; 1.2191x over previous
#include <cuda_runtime.h>
#include <cuda_fp16.h>
#include <math.h>
#include <stdint.h>

#define PP 7
#define NTOK 8192
#define DD 1024
#define HH 16
#define HDIM 64

// ---------------- scratch (device globals; no allocation allowed) --------
__device__ __align__(16) __half g_wqh[HH * DD];                // [h][k] fp16
__device__ float g_s0[HH];                                     // bk[hb] . q_h
__device__ __align__(16) float g_cvec[DD];                     // bv @ Wo + bo
__device__ __align__(16) float g_scores[(size_t)PP * NTOK * HH];   // [row=p*N+n][h]
__device__ __align__(16) __half g_xw_h[(size_t)HH * NTOK * DD];    // [h][n][d] fp16 (268 MB)
__device__ __align__(16) __half g_G_h[(size_t)NTOK * DD];          // attn_out fp16
__device__ __align__(16) __half g_wv_h[(size_t)DD * DD];           // Wv transposed [n][k] fp16
__device__ __align__(16) __half g_wo_h[(size_t)DD * DD];           // Wo transposed [n][k] fp16

// ---------------- K0a: wq[h][d] = sum_j Wk[d][64h+j] * q[h][j] (fp16 out) -
__global__ void k0_wq(const float* __restrict__ pq, const float* __restrict__ Wk,
                      const int* __restrict__ bidx) {
    int w = (blockIdx.x * blockDim.x + threadIdx.x) >> 5;
    int lane = threadIdx.x & 31;
    int h = w >> 10;
    int d = w & 1023;
    const float* q = pq + (size_t)bidx[0] * HH * HDIM + h * HDIM;
    const float* wrow = Wk + (size_t)d * DD + h * HDIM;
    float s = wrow[lane] * q[lane] + wrow[lane + 32] * q[lane + 32];
#pragma unroll
    for (int o = 16; o; o >>= 1) s += __shfl_xor_sync(0xFFFFFFFFu, s, o);
    if (lane == 0) g_wqh[h * DD + d] = __float2half(s);
}

// ---------------- K0b: cvec = bv @ Wo + bo ;  s0[h] = bk[hb].q_h ----------
__global__ void k0_misc(const float* __restrict__ pq, const float* __restrict__ bk,
                        const float* __restrict__ bv, const float* __restrict__ Wo,
                        const float* __restrict__ bo, const int* __restrict__ bidx) {
    int t = blockIdx.x * 256 + threadIdx.x;
    if (t < DD) {
        float acc = bo[t];
#pragma unroll 8
        for (int d = 0; d < DD; d++) acc = fmaf(bv[d], Wo[(size_t)d * DD + t], acc);
        g_cvec[t] = acc;
    }
    if (blockIdx.x == 4 && threadIdx.x < HH) {
        int h = threadIdx.x;
        const float* q = pq + (size_t)bidx[0] * HH * HDIM + h * HDIM;
        float s = 0.f;
#pragma unroll
        for (int j = 0; j < HDIM; j++) s = fmaf(bk[h * HDIM + j], q[j], s);
        g_s0[h] = s;
    }
}

// ---------------- K0c: transpose+convert Wv, Wo -> [n][k] fp16 ----------
__global__ void k0_conv(const float* __restrict__ Wv, const float* __restrict__ Wo) {
    __shared__ float tile[32][33];
    const float* W = blockIdx.z ? Wo : Wv;
    __half* O = blockIdx.z ? g_wo_h : g_wv_h;
    int bx = blockIdx.x * 32, by = blockIdx.y * 32;
#pragma unroll
    for (int yy = threadIdx.y; yy < 32; yy += 8)
        tile[yy][threadIdx.x] = W[(size_t)(by + yy) * DD + bx + threadIdx.x];
    __syncthreads();
#pragma unroll
    for (int yy = threadIdx.y; yy < 32; yy += 8)
        O[(size_t)(bx + yy) * DD + by + threadIdx.x] = __float2half(tile[threadIdx.x][yy]);
}

// ---------------- K1: scores via fp16 mma: [57344,1024]@[1024,16] ---------
// Static smem only: As[2][128][72] (36.9KB) + Ws[2][16][72] (4.6KB) = 41.5KB
#define K1_BM 128
#define K1_BK 64
#define K1_LDA 72   // halves per row (144 B); frag word idx ≡ 4g+tig (conflict-free)

__device__ __forceinline__ void mma_f16(float* d, const uint32_t* a, const uint32_t* b) {
    asm volatile(
        "mma.sync.aligned.m16n8k16.row.col.f32.f16.f16.f32 "
        "{%0,%1,%2,%3}, {%4,%5,%6,%7}, {%8,%9}, {%0,%1,%2,%3};"
        : "+f"(d[0]), "+f"(d[1]), "+f"(d[2]), "+f"(d[3])
        : "r"(a[0]), "r"(a[1]), "r"(a[2]), "r"(a[3]), "r"(b[0]), "r"(b[1]));
}

__global__ __launch_bounds__(256) void k1_mma(const float* __restrict__ x) {
    __shared__ __align__(16) __half As[2][K1_BM][K1_LDA];
    __shared__ __align__(16) __half Ws[2][HH][K1_LDA];

    int tid = threadIdx.x;
    int warp = tid >> 5, lane = tid & 31;
    int g = lane >> 2, tig = lane & 3;
    int rowA = tid >> 4;         // 0..15
    int cg = tid & 15;           // float4 column group within BK=64
    size_t row_base = (size_t)blockIdx.x * K1_BM;
    const float* Ab = x + row_base * DD;

    // W-tile loader: threads 0..127, one uint4 (8 halves) each
    int wrow = tid >> 3, wcg = (tid & 7) * 8;

    float acc[2][4];
#pragma unroll
    for (int nt = 0; nt < 2; nt++)
#pragma unroll
        for (int v = 0; v < 4; v++) acc[nt][v] = 0.f;

    float4 buf[8];
#pragma unroll
    for (int j = 0; j < 8; j++)
        buf[j] = *(const float4*)(Ab + (size_t)(rowA + 16 * j) * DD + cg * 4);
    uint4 wbuf;
    if (tid < 128) wbuf = *(const uint4*)(g_wqh + wrow * DD + wcg);

    const int NIT = DD / K1_BK;   // 16
    for (int kt = 0; kt < NIT; kt++) {
        int s = kt & 1;
        // STS converted A tile
#pragma unroll
        for (int j = 0; j < 8; j++) {
            __half2 h0 = __floats2half2_rn(buf[j].x, buf[j].y);
            __half2 h1 = __floats2half2_rn(buf[j].z, buf[j].w);
            uint2 u;
            u.x = *(uint32_t*)&h0;
            u.y = *(uint32_t*)&h1;
            *(uint2*)&As[s][rowA + 16 * j][cg * 4] = u;
        }
        if (tid < 128) *(uint4*)&Ws[s][wrow][wcg] = wbuf;
        __syncthreads();
        if (kt + 1 < NIT) {
            int k0 = (kt + 1) * K1_BK;
#pragma unroll
            for (int j = 0; j < 8; j++)
                buf[j] = *(const float4*)(Ab + (size_t)(rowA + 16 * j) * DD + k0 + cg * 4);
            if (tid < 128) wbuf = *(const uint4*)(g_wqh + wrow * DD + k0 + wcg);
        }
        int r0 = warp * 16;
#pragma unroll
        for (int ks = 0; ks < 4; ks++) {
            int kk = ks * 16;
            uint32_t a[4], b[2][2];
            a[0] = *(const uint32_t*)&As[s][r0 + g][kk + 2 * tig];
            a[1] = *(const uint32_t*)&As[s][r0 + g + 8][kk + 2 * tig];
            a[2] = *(const uint32_t*)&As[s][r0 + g][kk + 8 + 2 * tig];
            a[3] = *(const uint32_t*)&As[s][r0 + g + 8][kk + 8 + 2 * tig];
#pragma unroll
            for (int nt = 0; nt < 2; nt++) {
                b[nt][0] = *(const uint32_t*)&Ws[s][nt * 8 + g][kk + 2 * tig];
                b[nt][1] = *(const uint32_t*)&Ws[s][nt * 8 + g][kk + 8 + 2 * tig];
            }
            mma_f16(acc[0], a, b[0]);
            mma_f16(acc[1], a, b[1]);
        }
        __syncthreads();
    }

    // epilogue: scores = 0.125*(acc + s0[col])
    int r0 = warp * 16;
#pragma unroll
    for (int nt = 0; nt < 2; nt++) {
        int col = nt * 8 + 2 * tig;
        float2 s0v = *(const float2*)(g_s0 + col);
        size_t row = row_base + r0 + g;
        float2 lo = make_float2(0.125f * (acc[nt][0] + s0v.x), 0.125f * (acc[nt][1] + s0v.y));
        float2 hi = make_float2(0.125f * (acc[nt][2] + s0v.x), 0.125f * (acc[nt][3] + s0v.y));
        *(float2*)(g_scores + row * HH + col) = lo;
        *(float2*)(g_scores + (row + 8) * HH + col) = hi;
    }
}

// ---------------- K3a: softmax (fused) + XW_h[h][n][d] fp16 --------------
__global__ __launch_bounds__(256) void k3a_xw(const float* __restrict__ x) {
    int n = blockIdx.x;
    int t = threadIdx.x;
    __shared__ float raw[PP][HH];
    __shared__ float sa[HH * 8];
    if (t < PP * HH) {
        int p = t >> 4, h = t & 15;
        raw[p][h] = g_scores[((size_t)p * NTOK + n) * HH + h];
    }
    __syncthreads();
    if (t < HH) {
        float mx = -1e30f;
#pragma unroll
        for (int p = 0; p < PP; p++) mx = fmaxf(mx, raw[p][t]);
        float e[PP], sum = 0.f;
#pragma unroll
        for (int p = 0; p < PP; p++) {
            e[p] = expf(raw[p][t] - mx);
            sum += e[p];
        }
        float inv = 1.f / sum;
#pragma unroll
        for (int p = 0; p < PP; p++) sa[t * 8 + p] = e[p] * inv;
    }
    __syncthreads();
    const float4* xv = (const float4*)x;
    float4 xr[PP];
#pragma unroll
    for (int p = 0; p < PP; p++) xr[p] = xv[((size_t)p * NTOK + n) * 256 + t];
#pragma unroll
    for (int h = 0; h < HH; h++) {
        float4 o = make_float4(0.f, 0.f, 0.f, 0.f);
#pragma unroll
        for (int p = 0; p < PP; p++) {
            float a = sa[h * 8 + p];
            o.x = fmaf(a, xr[p].x, o.x);
            o.y = fmaf(a, xr[p].y, o.y);
            o.z = fmaf(a, xr[p].z, o.z);
            o.w = fmaf(a, xr[p].w, o.w);
        }
        __half2 h0 = __floats2half2_rn(o.x, o.y);
        __half2 h1 = __floats2half2_rn(o.z, o.w);
        uint2 pk;
        pk.x = *(uint32_t*)&h0;
        pk.y = *(uint32_t*)&h1;
        *(uint2*)(g_xw_h + ((size_t)h * NTOK + n) * DD + t * 4) = pk;
    }
}

// ---------------- fp16 tensor-core GEMM, 128x64x32, cp.async 2-stage ------
#define BM 128
#define BN 64
#define BK 32
#define LDS_A 40

__device__ __forceinline__ void cp16(void* dst, const void* src) {
    uint32_t d = (uint32_t)__cvta_generic_to_shared(dst);
    asm volatile("cp.async.cg.shared.global [%0], [%1], 16;" :: "r"(d), "l"(src));
}

__global__ __launch_bounds__(256) void gemm_f16(int mode, float* __restrict__ Cout) {
    __shared__ __align__(16) __half As[2][BM][LDS_A];
    __shared__ __align__(16) __half Bs[2][BN][LDS_A];
    int by = blockIdx.y;
    const __half* A = (mode == 0) ? (g_xw_h + (size_t)by * NTOK * DD) : g_G_h;
    const __half* Bw = (mode == 0) ? g_wv_h : g_wo_h;
    const __half* Ab = A + (size_t)blockIdx.x * BM * DD;
    const __half* Bb = Bw + (size_t)by * BN * DD;

    int tid = threadIdx.x;
    int warp = tid >> 5, lane = tid & 31;
    int wm = warp & 3, wn = warp >> 2;
    int g = lane >> 2, tig = lane & 3;
    int rb = wm * 32, nb0 = wn * 32;

    float acc[2][4][4];
#pragma unroll
    for (int i = 0; i < 2; i++)
#pragma unroll
        for (int j = 0; j < 4; j++)
#pragma unroll
            for (int v = 0; v < 4; v++) acc[i][j][v] = 0.f;

    int ar = tid >> 2, ac = (tid & 3) * 8;
    int ar2 = (tid + 256) >> 2;
    int br = tid >> 2, bc = (tid & 3) * 8;

#define LOAD_STAGE(s, k0)                                                     \
    do {                                                                      \
        cp16(&As[s][ar][ac], Ab + (size_t)ar * DD + (k0) + ac);               \
        cp16(&As[s][ar2][ac], Ab + (size_t)ar2 * DD + (k0) + ac);             \
        cp16(&Bs[s][br][bc], Bb + (size_t)br * DD + (k0) + bc);               \
        asm volatile("cp.async.commit_group;");                               \
    } while (0)

    LOAD_STAGE(0, 0);
    const int NIT = DD / BK;
    for (int it = 0; it < NIT; it++) {
        if (it + 1 < NIT) {
            LOAD_STAGE((it + 1) & 1, (it + 1) * BK);
            asm volatile("cp.async.wait_group 1;");
        } else {
            asm volatile("cp.async.wait_group 0;");
        }
        __syncthreads();
        int s = it & 1;
#pragma unroll
        for (int kt = 0; kt < 2; kt++) {
            int kk = kt * 16;
            uint32_t a[2][4], b[4][2];
#pragma unroll
            for (int mt = 0; mt < 2; mt++) {
                int r0 = rb + mt * 16;
                a[mt][0] = *(const uint32_t*)&As[s][r0 + g][kk + 2 * tig];
                a[mt][1] = *(const uint32_t*)&As[s][r0 + g + 8][kk + 2 * tig];
                a[mt][2] = *(const uint32_t*)&As[s][r0 + g][kk + 8 + 2 * tig];
                a[mt][3] = *(const uint32_t*)&As[s][r0 + g + 8][kk + 8 + 2 * tig];
            }
#pragma unroll
            for (int nt = 0; nt < 4; nt++) {
                int n0 = nb0 + nt * 8;
                b[nt][0] = *(const uint32_t*)&Bs[s][n0 + g][kk + 2 * tig];
                b[nt][1] = *(const uint32_t*)&Bs[s][n0 + g][kk + 8 + 2 * tig];
            }
#pragma unroll
            for (int mt = 0; mt < 2; mt++)
#pragma unroll
                for (int nt = 0; nt < 4; nt++) mma_f16(acc[mt][nt], a[mt], b[nt]);
        }
        __syncthreads();
    }

#pragma unroll
    for (int mt = 0; mt < 2; mt++) {
#pragma unroll
        for (int nt = 0; nt < 4; nt++) {
            size_t row0 = (size_t)blockIdx.x * BM + rb + mt * 16 + g;
            int col = by * BN + nb0 + nt * 8 + tig * 2;
            if (mode == 0) {
                __half2 lo = __floats2half2_rn(acc[mt][nt][0], acc[mt][nt][1]);
                __half2 hi = __floats2half2_rn(acc[mt][nt][2], acc[mt][nt][3]);
                *(__half2*)(g_G_h + row0 * DD + col) = lo;
                *(__half2*)(g_G_h + (row0 + 8) * DD + col) = hi;
            } else {
                float2 bb = *(const float2*)(g_cvec + col);
                float2 lo = make_float2(acc[mt][nt][0] + bb.x, acc[mt][nt][1] + bb.y);
                float2 hi = make_float2(acc[mt][nt][2] + bb.x, acc[mt][nt][3] + bb.y);
                *(float2*)(Cout + row0 * DD + col) = lo;
                *(float2*)(Cout + (row0 + 8) * DD + col) = hi;
            }
        }
    }
}

// ---------------- launch ---------------------------------------------------
extern "C" void kernel_launch(void* const* d_in, const int* in_sizes, int n_in,
                              void* d_out, int out_size) {
    const float* prev = (const float*)d_in[0];
    const float* pq   = (const float*)d_in[1];
    const float* Wk   = (const float*)d_in[2];
    const float* bk   = (const float*)d_in[3];
    const float* Wv   = (const float*)d_in[4];
    const float* bv   = (const float*)d_in[5];
    const float* Wo   = (const float*)d_in[6];
    const float* bo   = (const float*)d_in[7];
    const int*   bidx = (const int*)d_in[8];
    float* out = (float*)d_out;

    k0_wq<<<2048, 256>>>(pq, Wk, bidx);
    k0_misc<<<5, 256>>>(pq, bk, bv, Wo, bo, bidx);
    k0_conv<<<dim3(32, 32, 2), dim3(32, 8)>>>(Wv, Wo);
    k1_mma<<<PP * NTOK / K1_BM, 256>>>(prev);
    k3a_xw<<<NTOK, 256>>>(prev);
    gemm_f16<<<dim3(NTOK / BM, 16), 256>>>(0, out);
    gemm_f16<<<dim3(NTOK / BM, 16), 256>>>(1, out);
}